// round 10
// baseline (speedup 1.0000x reference)
#include <cuda_runtime.h>
#include <cuda_bf16.h>

#define TPB 256
#define MAX_ATOMS 100000
#define NB 64
#define NB2 32   // float2 pairs per atom
#define NWARP (TPB / 32)
#define TR_ATOMS 32

// Interleaved batch-fastest positions: g_pos[atom][comp][pair] as float2.
// One address per atom; x/y/z at +0/+256/+512 bytes. Lane l covers batches
// 2l, 2l+1 -> every load is a coalesced 256B run.
__device__ float2 g_pos[(size_t)MAX_ATOMS * 3 * NB2];

// Tiled transpose: pos[b][atom][3] -> g_pos[atom][comp][pair]. Zeroes out[].
__global__ void transpose_kernel(const float* __restrict__ pos, int n_atoms,
                                 float* __restrict__ out) {
    __shared__ float tile[NB][TR_ATOMS * 3 + 1];   // [64][97]
    int tid = threadIdx.x;
    int atom_base = blockIdx.x * TR_ATOMS;

    if (blockIdx.x == 0 && tid < NB) out[tid] = 0.0f;

    int lim3 = n_atoms * 3;
    int base3 = atom_base * 3;
    #pragma unroll
    for (int idx = tid; idx < NB * (TR_ATOMS * 3 / 4); idx += TPB) {
        int b = idx / (TR_ATOMS * 3 / 4);
        int q = idx - b * (TR_ATOMS * 3 / 4);
        int g = base3 + q * 4;
        if (g + 3 < lim3) {
            float4 v = __ldg((const float4*)(pos + (size_t)b * lim3 + g));
            tile[b][q * 4]     = v.x;
            tile[b][q * 4 + 1] = v.y;
            tile[b][q * 4 + 2] = v.z;
            tile[b][q * 4 + 3] = v.w;
        } else {
            for (int k = 0; k < 4 && g + k < lim3; k++)
                tile[b][q * 4 + k] = __ldg(&pos[(size_t)b * lim3 + g + k]);
        }
    }
    __syncthreads();
    #pragma unroll
    for (int idx = tid; idx < 3 * TR_ATOMS * NB2; idx += TPB) {
        int comp = idx >> 10;
        int rem  = idx & 1023;
        int atom = rem >> 5;
        int l    = rem & 31;
        int ga = atom_base + atom;
        if (ga < n_atoms) {
            float2 v = make_float2(tile[2 * l][atom * 3 + comp],
                                   tile[2 * l + 1][atom * 3 + comp]);
            g_pos[(size_t)ga * (3 * NB2) + comp * NB2 + l] = v;
        }
    }
}

// ---- packed f32x2 helpers (one SASS op per batch-pair) ----
typedef unsigned long long p2;

__device__ __forceinline__ p2 PK2(float lo, float hi) {
    p2 r;
    asm("mov.b64 %0, {%1, %2};" : "=l"(r)
        : "r"(__float_as_uint(lo)), "r"(__float_as_uint(hi)));
    return r;
}
__device__ __forceinline__ void UPK2(p2 v, float& lo, float& hi) {
    unsigned a, b;
    asm("mov.b64 {%0, %1}, %2;" : "=r"(a), "=r"(b) : "l"(v));
    lo = __uint_as_float(a);
    hi = __uint_as_float(b);
}
__device__ __forceinline__ p2 pc(float v) {          // broadcast constant
    unsigned u = __float_as_uint(v);
    return ((p2)u << 32) | u;
}
__device__ __forceinline__ p2 padd(p2 a, p2 b) {
    p2 r; asm("add.rn.f32x2 %0, %1, %2;" : "=l"(r) : "l"(a), "l"(b)); return r;
}
__device__ __forceinline__ p2 pmul(p2 a, p2 b) {
    p2 r; asm("mul.rn.f32x2 %0, %1, %2;" : "=l"(r) : "l"(a), "l"(b)); return r;
}
__device__ __forceinline__ p2 pfma(p2 a, p2 b, p2 c) {
    p2 r; asm("fma.rn.f32x2 %0, %1, %2, %3;" : "=l"(r) : "l"(a), "l"(b), "l"(c)); return r;
}
__device__ __forceinline__ p2 pneg(p2 a) { return a ^ 0x8000000080000000ULL; }
// a - b == fma(-b, 1...) ; use fma(b, -1, a): exact (b*-1 exact, single rounding add)
__device__ __forceinline__ p2 psub(p2 a, p2 b) { return pfma(b, pc(-1.0f), a); }
__device__ __forceinline__ p2 pdot3(p2 ax, p2 ay, p2 az, p2 bx, p2 by, p2 bz) {
    return pfma(ax, bx, pfma(ay, by, pmul(az, bz)));
}
__device__ __forceinline__ p2 prsqrt(p2 a) {
    float lo, hi; UPK2(a, lo, hi);
    return PK2(rsqrtf(lo), rsqrtf(hi));
}

__device__ __forceinline__ void load_atom(int a, int lane, p2& x, p2& y, p2& z) {
    const p2* p = (const p2*)g_pos + (size_t)a * (3 * NB2) + lane;
    x = __ldg(p);
    y = __ldg(p + NB2);
    z = __ldg(p + 2 * NB2);
}

// Abramowitz-Stegun 4.4.46 degree-7: |err| ~ 1e-7 over [-1, 1].
__device__ __forceinline__ float fast_acos(float x) {
    float a = fabsf(x);
    float p = fmaf(a, -0.0012624911f, 0.0066700901f);
    p = fmaf(a, p, -0.0170881256f);
    p = fmaf(a, p, 0.0308918810f);
    p = fmaf(a, p, -0.0501743046f);
    p = fmaf(a, p, 0.0889789874f);
    p = fmaf(a, p, -0.2145988016f);
    p = fmaf(a, p, 1.5707963050f);
    float r = p * sqrtf(1.0f - a);
    return (x < 0.0f) ? (3.14159265358979f - r) : r;
}

// Minimax odd atan on [0,1] + quadrant reduction; |err| ~ 1e-6.
__device__ __forceinline__ float fast_atan2(float y, float x) {
    float ax = fabsf(x), ay = fabsf(y);
    float mx = fmaxf(ax, ay), mn = fminf(ax, ay);
    float z = __fdividef(mn, mx);
    float z2 = z * z;
    float p = fmaf(z2, -0.0117212f, 0.0526533f);
    p = fmaf(z2, p, -0.1164329f);
    p = fmaf(z2, p, 0.1935435f);
    p = fmaf(z2, p, -0.3326235f);
    p = fmaf(z2, p, 0.9999773f);
    float r = p * z;
    if (ay > ax) r = 1.57079632679f - r;
    if (x < 0.0f) r = 3.14159265359f - r;
    return copysignf(r, y);
}

// Raw dihedral numerator/denominator; phi = atan2(Y, X). All packed f32x2.
__device__ __forceinline__ void dihedral_xy(int a0, int a1, int a2, int a3, int lane,
                                            p2& X, p2& Y) {
    p2 x0, y0, z0, x1, y1, z1, x2, y2, z2, x3, y3, z3;
    load_atom(a0, lane, x0, y0, z0);
    load_atom(a1, lane, x1, y1, z1);
    load_atom(a2, lane, x2, y2, z2);
    load_atom(a3, lane, x3, y3, z3);
    p2 b0x = psub(x0, x1), b0y = psub(y0, y1), b0z = psub(z0, z1);
    p2 b1x = psub(x2, x1), b1y = psub(y2, y1), b1z = psub(z2, z1);
    p2 b2x = psub(x3, x2), b2y = psub(y3, y2), b2z = psub(z3, z2);
    p2 inv = prsqrt(pdot3(b1x, b1y, b1z, b1x, b1y, b1z));
    b1x = pmul(b1x, inv); b1y = pmul(b1y, inv); b1z = pmul(b1z, inv);
    p2 nd0 = pneg(pdot3(b0x, b0y, b0z, b1x, b1y, b1z));
    p2 nd2 = pneg(pdot3(b2x, b2y, b2z, b1x, b1y, b1z));
    p2 vx = pfma(nd0, b1x, b0x), vy = pfma(nd0, b1y, b0y), vz = pfma(nd0, b1z, b0z);
    p2 wx = pfma(nd2, b1x, b2x), wy = pfma(nd2, b1y, b2y), wz = pfma(nd2, b1z, b2z);
    X = pdot3(vx, vy, vz, wx, wy, wz);
    // cross(b1, v): cx = b1y*vz - b1z*vy, etc. (one pmul + one pfma w/ negated b1)
    p2 nb1x = pneg(b1x), nb1y = pneg(b1y), nb1z = pneg(b1z);
    p2 cx = pfma(nb1z, vy, pmul(b1y, vz));
    p2 cy = pfma(nb1x, vz, pmul(b1z, vx));
    p2 cz = pfma(nb1y, vx, pmul(b1x, vy));
    Y = pdot3(cx, cy, cz, wx, wy, wz);
}

// Partitioned kernel: 1D grid split into 4 contiguous category ranges.
__global__ void energy_kernel(
    const int* __restrict__ bond_idcs, const int* __restrict__ bond_type,
    const float* __restrict__ equ_bond, const float* __restrict__ k_bond, int n_bond,
    const int* __restrict__ angle_idcs, const int* __restrict__ angle_type,
    const float* __restrict__ equ_angle, const float* __restrict__ k_angle, int n_angle,
    const int* __restrict__ improper_idcs, const int* __restrict__ improper_type,
    const float* __restrict__ equ_improper, const float* __restrict__ k_improper, int n_improper,
    const int* __restrict__ proper_idcs, const float* __restrict__ proper_phase,
    const float* __restrict__ proper_const, const float* __restrict__ proper_mul, int n_proper,
    int gb, int ga, int gi,
    float* __restrict__ out)
{
    int lane = threadIdx.x & 31;
    int warp = threadIdx.x >> 5;

    int cat, bstart, bcount;
    int bx = blockIdx.x;
    if (bx < gb)      { cat = 0; bstart = 0;  bcount = gb; }
    else if (bx < ga) { cat = 1; bstart = gb; bcount = ga - gb; }
    else if (bx < gi) { cat = 2; bstart = ga; bcount = gi - ga; }
    else              { cat = 3; bstart = gi; bcount = gridDim.x - gi; }

    int warp_g = (bx - bstart) * NWARP + warp;
    int nwarps = bcount * NWARP;
    float ex = 0.0f, ey = 0.0f;

    if (cat == 0) {                 // bonds
        for (int t = warp_g; t < n_bond; t += nwarps) {
            int a0 = __ldg(&bond_idcs[2 * t]);
            int a1 = __ldg(&bond_idcs[2 * t + 1]);
            int ty = __ldg(&bond_type[t]);
            float eq = __ldg(&equ_bond[ty]);
            float kb = __ldg(&k_bond[ty]);
            p2 x0, y0, z0, x1, y1, z1;
            load_atom(a0, lane, x0, y0, z0);
            load_atom(a1, lane, x1, y1, z1);
            p2 dx = psub(x0, x1), dy = psub(y0, y1), dz = psub(z0, z1);
            p2 r2 = pdot3(dx, dy, dz, dx, dy, dz);
            float rl, rh; UPK2(r2, rl, rh);
            float ddl = sqrtf(rl) - eq;
            float ddh = sqrtf(rh) - eq;
            ex = fmaf(kb * ddl, ddl, ex);
            ey = fmaf(kb * ddh, ddh, ey);
        }
    } else if (cat == 1) {          // angles
        for (int t = warp_g; t < n_angle; t += nwarps) {
            int a0 = __ldg(&angle_idcs[3 * t]);
            int a1 = __ldg(&angle_idcs[3 * t + 1]);
            int a2 = __ldg(&angle_idcs[3 * t + 2]);
            int ty = __ldg(&angle_type[t]);
            float eq = __ldg(&equ_angle[ty]);
            float ka = __ldg(&k_angle[ty]);
            p2 x0, y0, z0, x1, y1, z1, x2, y2, z2;
            load_atom(a0, lane, x0, y0, z0);
            load_atom(a1, lane, x1, y1, z1);
            load_atom(a2, lane, x2, y2, z2);
            p2 v1x = psub(x0, x1), v1y = psub(y0, y1), v1z = psub(z0, z1);
            p2 v2x = psub(x2, x1), v2y = psub(y2, y1), v2z = psub(z2, z1);
            p2 n1 = pdot3(v1x, v1y, v1z, v1x, v1y, v1z);
            p2 n2 = pdot3(v2x, v2y, v2z, v2x, v2y, v2z);
            p2 dt = pdot3(v1x, v1y, v1z, v2x, v2y, v2z);
            p2 c = pmul(pmul(dt, prsqrt(n1)), prsqrt(n2));
            float cl, ch; UPK2(c, cl, ch);
            cl = fminf(1.0f, fmaxf(-1.0f, cl));
            ch = fminf(1.0f, fmaxf(-1.0f, ch));
            float ddl = fast_acos(cl) - eq;
            float ddh = fast_acos(ch) - eq;
            ex = fmaf(ka * ddl, ddl, ex);
            ey = fmaf(ka * ddh, ddh, ey);
        }
    } else if (cat == 2) {          // impropers
        for (int t = warp_g; t < n_improper; t += nwarps) {
            int4 a = __ldg((const int4*)improper_idcs + t);
            int ty = __ldg(&improper_type[t]);
            float eq = __ldg(&equ_improper[ty]);
            float ki = __ldg(&k_improper[ty]);
            p2 X, Y;
            dihedral_xy(a.x, a.y, a.z, a.w, lane, X, Y);
            float Xl, Xh, Yl, Yh;
            UPK2(X, Xl, Xh); UPK2(Y, Yl, Yh);
            float ddl = fast_atan2(Yl, Xl) - eq;
            float ddh = fast_atan2(Yh, Xh) - eq;
            ex = fmaf(ki * ddl, ddl, ex);
            ey = fmaf(ki * ddh, ddh, ey);
        }
    } else {                        // propers
        for (int t = warp_g; t < n_proper; t += nwarps) {
            int4 a = __ldg((const int4*)proper_idcs + t);
            float ph = __ldg(&proper_phase[t]);
            float cst = __ldg(&proper_const[t]);
            float ml = __ldg(&proper_mul[t]);
            p2 X, Y;
            dihedral_xy(a.x, a.y, a.z, a.w, lane, X, Y);
            if (ml == 2.0f && ph == 0.0f) {
                // cst*(1+cos(2*atan2(y,x))) = 2*cst*x^2/(x^2+y^2)
                p2 xx = pmul(X, X);
                p2 den = pfma(Y, Y, xx);
                float xxl, xxh, dl, dh;
                UPK2(xx, xxl, xxh); UPK2(den, dl, dh);
                float c2 = 2.0f * cst;
                ex = fmaf(c2 * xxl, 1.0f / dl, ex);
                ey = fmaf(c2 * xxh, 1.0f / dh, ey);
            } else {
                float Xl, Xh, Yl, Yh;
                UPK2(X, Xl, Xh); UPK2(Y, Yl, Yh);
                float phil = fast_atan2(Yl, Xl);
                float phih = fast_atan2(Yh, Xh);
                ex += cst * (1.0f + cosf(fmaf(ml, phil, -ph)));
                ey += cst * (1.0f + cosf(fmaf(ml, phih, -ph)));
            }
        }
    }

    // Per-warp private slots, then fold.
    __shared__ float sh[NWARP][NB];
    sh[warp][2 * lane]     = ex;
    sh[warp][2 * lane + 1] = ey;
    __syncthreads();
    if (threadIdx.x < NB) {
        float s = 0.0f;
        #pragma unroll
        for (int w = 0; w < NWARP; w++) s += sh[w][threadIdx.x];
        atomicAdd(&out[threadIdx.x], s);
    }
}

extern "C" void kernel_launch(void* const* d_in, const int* in_sizes, int n_in,
                              void* d_out, int out_size) {
    const float* pos            = (const float*)d_in[0];
    const int*   bond_idcs      = (const int*)d_in[1];
    const int*   bond_type      = (const int*)d_in[2];
    const float* equ_bond       = (const float*)d_in[3];
    const float* k_bond         = (const float*)d_in[4];
    const int*   angle_idcs     = (const int*)d_in[5];
    const int*   angle_type     = (const int*)d_in[6];
    const float* equ_angle      = (const float*)d_in[7];
    const float* k_angle        = (const float*)d_in[8];
    const int*   improper_idcs  = (const int*)d_in[9];
    const int*   improper_type  = (const int*)d_in[10];
    const float* equ_improper   = (const float*)d_in[11];
    const float* k_improper     = (const float*)d_in[12];
    const int*   proper_idcs    = (const int*)d_in[13];
    const float* proper_phase   = (const float*)d_in[14];
    const float* proper_const   = (const float*)d_in[15];
    const float* proper_mul     = (const float*)d_in[16];
    float* out = (float*)d_out;

    int B          = out_size;              // 64
    int n_bond     = in_sizes[2];
    int n_angle    = in_sizes[6];
    int n_improper = in_sizes[10];
    int n_proper   = in_sizes[14];
    int n_atoms    = in_sizes[0] / (3 * B);

    int tr_blocks = (n_atoms + TR_ATOMS - 1) / TR_ATOMS;
    transpose_kernel<<<tr_blocks, TPB>>>(pos, n_atoms, out);

    // Single wave: 888 blocks = 6 blocks/SM x 148 SMs.
    // Cost weights per term: bond 6, angle 10, improper 15, proper 12.
    long long wb = 6LL * n_bond, wa = 10LL * n_angle, wi = 15LL * n_improper, wp = 12LL * n_proper;
    long long wt = wb + wa + wi + wp;
    int total_blocks = 888;
    int gb  = (int)(total_blocks * wb / wt); if (gb < 1) gb = 1;
    int ga_ = (int)(total_blocks * wa / wt); if (ga_ < 1) ga_ = 1;
    int gi_ = (int)(total_blocks * wi / wt); if (gi_ < 1) gi_ = 1;
    int ga = gb + ga_;
    int gi = ga + gi_;
    if (gi >= total_blocks) gi = total_blocks - 1;

    energy_kernel<<<total_blocks, TPB>>>(
        bond_idcs, bond_type, equ_bond, k_bond, n_bond,
        angle_idcs, angle_type, equ_angle, k_angle, n_angle,
        improper_idcs, improper_type, equ_improper, k_improper, n_improper,
        proper_idcs, proper_phase, proper_const, proper_mul, n_proper,
        gb, ga, gi, out);
}

// round 11
// speedup vs baseline: 1.0875x; 1.0875x over previous
#include <cuda_runtime.h>
#include <cuda_bf16.h>

#define TPB 256
#define MAX_ATOMS 100000
#define NB 64
#define NB2 32   // float2 pairs per atom
#define NWARP (TPB / 32)
#define TR_ATOMS 32

// Interleaved batch-fastest positions: g_pos[atom][comp][pair] as float2.
// One address per atom; x/y/z at +0/+256/+512 bytes. Lane l covers batches
// 2l, 2l+1 -> every load is a coalesced 256B run.
__device__ float2 g_pos[(size_t)MAX_ATOMS * 3 * NB2];

// Tiled transpose: pos[b][atom][3] -> g_pos[atom][comp][pair]. Zeroes out[].
__global__ void transpose_kernel(const float* __restrict__ pos, int n_atoms,
                                 float* __restrict__ out) {
    __shared__ float tile[NB][TR_ATOMS * 3 + 1];   // [64][97]
    int tid = threadIdx.x;
    int atom_base = blockIdx.x * TR_ATOMS;

    if (blockIdx.x == 0 && tid < NB) out[tid] = 0.0f;

    int lim3 = n_atoms * 3;
    int base3 = atom_base * 3;
    #pragma unroll
    for (int idx = tid; idx < NB * (TR_ATOMS * 3 / 4); idx += TPB) {
        int b = idx / (TR_ATOMS * 3 / 4);
        int q = idx - b * (TR_ATOMS * 3 / 4);
        int g = base3 + q * 4;
        if (g + 3 < lim3) {
            float4 v = __ldg((const float4*)(pos + (size_t)b * lim3 + g));
            tile[b][q * 4]     = v.x;
            tile[b][q * 4 + 1] = v.y;
            tile[b][q * 4 + 2] = v.z;
            tile[b][q * 4 + 3] = v.w;
        } else {
            for (int k = 0; k < 4 && g + k < lim3; k++)
                tile[b][q * 4 + k] = __ldg(&pos[(size_t)b * lim3 + g + k]);
        }
    }
    __syncthreads();
    #pragma unroll
    for (int idx = tid; idx < 3 * TR_ATOMS * NB2; idx += TPB) {
        int comp = idx >> 10;
        int rem  = idx & 1023;
        int atom = rem >> 5;
        int l    = rem & 31;
        int ga = atom_base + atom;
        if (ga < n_atoms) {
            float2 v = make_float2(tile[2 * l][atom * 3 + comp],
                                   tile[2 * l + 1][atom * 3 + comp]);
            g_pos[(size_t)ga * (3 * NB2) + comp * NB2 + l] = v;
        }
    }
}

// ---- float2 elementwise helpers ----
__device__ __forceinline__ float2 f2sub(float2 a, float2 b) { return make_float2(a.x - b.x, a.y - b.y); }
__device__ __forceinline__ float2 f2mul(float2 a, float2 b) { return make_float2(a.x * b.x, a.y * b.y); }
__device__ __forceinline__ float2 f2fma(float2 a, float2 b, float2 c) {
    return make_float2(fmaf(a.x, b.x, c.x), fmaf(a.y, b.y, c.y));
}
__device__ __forceinline__ float2 f2nfma(float2 a, float2 b, float2 c) { // c - a*b
    return make_float2(fmaf(-a.x, b.x, c.x), fmaf(-a.y, b.y, c.y));
}
__device__ __forceinline__ float2 f2rsqrt(float2 a) { return make_float2(rsqrtf(a.x), rsqrtf(a.y)); }

__device__ __forceinline__ void load_atom(int a, int lane, float2& x, float2& y, float2& z) {
    const float2* p = g_pos + (size_t)a * (3 * NB2) + lane;
    x = __ldg(p);
    y = __ldg(p + NB2);
    z = __ldg(p + 2 * NB2);
}

__device__ __forceinline__ float2 f2dot3(float2 ax, float2 ay, float2 az,
                                         float2 bx, float2 by, float2 bz) {
    return f2fma(ax, bx, f2fma(ay, by, f2mul(az, bz)));
}

// Abramowitz-Stegun 4.4.46 degree-7: |err| ~ 1e-7 over [-1, 1].
__device__ __forceinline__ float fast_acos(float x) {
    float a = fabsf(x);
    float p = fmaf(a, -0.0012624911f, 0.0066700901f);
    p = fmaf(a, p, -0.0170881256f);
    p = fmaf(a, p, 0.0308918810f);
    p = fmaf(a, p, -0.0501743046f);
    p = fmaf(a, p, 0.0889789874f);
    p = fmaf(a, p, -0.2145988016f);
    p = fmaf(a, p, 1.5707963050f);
    float r = p * sqrtf(1.0f - a);
    return (x < 0.0f) ? (3.14159265358979f - r) : r;
}

// Minimax odd atan on [0,1] + quadrant reduction; |err| ~ 1e-6.
__device__ __forceinline__ float fast_atan2(float y, float x) {
    float ax = fabsf(x), ay = fabsf(y);
    float mx = fmaxf(ax, ay), mn = fminf(ax, ay);
    float z = __fdividef(mn, mx);
    float z2 = z * z;
    float p = fmaf(z2, -0.0117212f, 0.0526533f);
    p = fmaf(z2, p, -0.1164329f);
    p = fmaf(z2, p, 0.1935435f);
    p = fmaf(z2, p, -0.3326235f);
    p = fmaf(z2, p, 0.9999773f);
    float r = p * z;
    if (ay > ax) r = 1.57079632679f - r;
    if (x < 0.0f) r = 3.14159265359f - r;
    return copysignf(r, y);
}

// Raw dihedral numerator/denominator (x, y) for a batch-pair; phi = atan2(y, x).
__device__ __forceinline__ void dihedral_xy(int a0, int a1, int a2, int a3, int lane,
                                            float2& X, float2& Y) {
    float2 x0, y0, z0, x1, y1, z1, x2, y2, z2, x3, y3, z3;
    load_atom(a0, lane, x0, y0, z0);
    load_atom(a1, lane, x1, y1, z1);
    load_atom(a2, lane, x2, y2, z2);
    load_atom(a3, lane, x3, y3, z3);
    float2 b0x = f2sub(x0, x1), b0y = f2sub(y0, y1), b0z = f2sub(z0, z1);
    float2 b1x = f2sub(x2, x1), b1y = f2sub(y2, y1), b1z = f2sub(z2, z1);
    float2 b2x = f2sub(x3, x2), b2y = f2sub(y3, y2), b2z = f2sub(z3, z2);
    float2 inv = f2rsqrt(f2dot3(b1x, b1y, b1z, b1x, b1y, b1z));
    b1x = f2mul(b1x, inv); b1y = f2mul(b1y, inv); b1z = f2mul(b1z, inv);
    float2 d0 = f2dot3(b0x, b0y, b0z, b1x, b1y, b1z);
    float2 d2 = f2dot3(b2x, b2y, b2z, b1x, b1y, b1z);
    float2 vx = f2nfma(d0, b1x, b0x), vy = f2nfma(d0, b1y, b0y), vz = f2nfma(d0, b1z, b0z);
    float2 wx = f2nfma(d2, b1x, b2x), wy = f2nfma(d2, b1y, b2y), wz = f2nfma(d2, b1z, b2z);
    X = f2dot3(vx, vy, vz, wx, wy, wz);
    float2 cx = f2sub(f2mul(b1y, vz), f2mul(b1z, vy));
    float2 cy = f2sub(f2mul(b1z, vx), f2mul(b1x, vz));
    float2 cz = f2sub(f2mul(b1x, vy), f2mul(b1y, vx));
    Y = f2dot3(cx, cy, cz, wx, wy, wz);
}

// ---- per-term accumulate bodies (inlined; independent calls can overlap) ----
__device__ __forceinline__ void angle_term(
    int t, int lane,
    const int* __restrict__ idcs, const int* __restrict__ type,
    const float* __restrict__ equ, const float* __restrict__ kk,
    float& ex, float& ey)
{
    int a0 = __ldg(&idcs[3 * t]);
    int a1 = __ldg(&idcs[3 * t + 1]);
    int a2 = __ldg(&idcs[3 * t + 2]);
    int ty = __ldg(&type[t]);
    float eq = __ldg(&equ[ty]);
    float ka = __ldg(&kk[ty]);
    float2 x0, y0, z0, x1, y1, z1, x2, y2, z2;
    load_atom(a0, lane, x0, y0, z0);
    load_atom(a1, lane, x1, y1, z1);
    load_atom(a2, lane, x2, y2, z2);
    float2 v1x = f2sub(x0, x1), v1y = f2sub(y0, y1), v1z = f2sub(z0, z1);
    float2 v2x = f2sub(x2, x1), v2y = f2sub(y2, y1), v2z = f2sub(z2, z1);
    float2 n1 = f2dot3(v1x, v1y, v1z, v1x, v1y, v1z);
    float2 n2 = f2dot3(v2x, v2y, v2z, v2x, v2y, v2z);
    float2 dt = f2dot3(v1x, v1y, v1z, v2x, v2y, v2z);
    float2 c = f2mul(f2mul(dt, f2rsqrt(n1)), f2rsqrt(n2));
    float cx = fminf(1.0f, fmaxf(-1.0f, c.x));
    float cy = fminf(1.0f, fmaxf(-1.0f, c.y));
    float ddx = fast_acos(cx) - eq;
    float ddy = fast_acos(cy) - eq;
    ex = fmaf(ka * ddx, ddx, ex);
    ey = fmaf(ka * ddy, ddy, ey);
}

__device__ __forceinline__ void improper_term(
    int t, int lane,
    const int* __restrict__ idcs, const int* __restrict__ type,
    const float* __restrict__ equ, const float* __restrict__ kk,
    float& ex, float& ey)
{
    int4 a = __ldg((const int4*)idcs + t);
    int ty = __ldg(&type[t]);
    float eq = __ldg(&equ[ty]);
    float ki = __ldg(&kk[ty]);
    float2 X, Y;
    dihedral_xy(a.x, a.y, a.z, a.w, lane, X, Y);
    float ddx = fast_atan2(Y.x, X.x) - eq;
    float ddy = fast_atan2(Y.y, X.y) - eq;
    ex = fmaf(ki * ddx, ddx, ex);
    ey = fmaf(ki * ddy, ddy, ey);
}

__device__ __forceinline__ void proper_term(
    int t, int lane,
    const int* __restrict__ idcs, const float* __restrict__ phase,
    const float* __restrict__ cst_arr, const float* __restrict__ mul_arr,
    float& ex, float& ey)
{
    int4 a = __ldg((const int4*)idcs + t);
    float ph = __ldg(&phase[t]);
    float cst = __ldg(&cst_arr[t]);
    float ml = __ldg(&mul_arr[t]);
    float2 X, Y;
    dihedral_xy(a.x, a.y, a.z, a.w, lane, X, Y);
    if (ml == 2.0f && ph == 0.0f) {
        float c2x = 2.0f * cst;
        ex = fmaf(c2x * X.x, X.x / fmaf(X.x, X.x, Y.x * Y.x), ex);
        ey = fmaf(c2x * X.y, X.y / fmaf(X.y, X.y, Y.y * Y.y), ey);
    } else {
        float phix = fast_atan2(Y.x, X.x);
        float phiy = fast_atan2(Y.y, X.y);
        ex += cst * (1.0f + cosf(fmaf(ml, phix, -ph)));
        ey += cst * (1.0f + cosf(fmaf(ml, phiy, -ph)));
    }
}

// Partitioned kernel: 1D grid split into 4 contiguous category ranges.
// Heavy categories process 2 independent terms per iteration for 2x MLP.
__global__ void energy_kernel(
    const int* __restrict__ bond_idcs, const int* __restrict__ bond_type,
    const float* __restrict__ equ_bond, const float* __restrict__ k_bond, int n_bond,
    const int* __restrict__ angle_idcs, const int* __restrict__ angle_type,
    const float* __restrict__ equ_angle, const float* __restrict__ k_angle, int n_angle,
    const int* __restrict__ improper_idcs, const int* __restrict__ improper_type,
    const float* __restrict__ equ_improper, const float* __restrict__ k_improper, int n_improper,
    const int* __restrict__ proper_idcs, const float* __restrict__ proper_phase,
    const float* __restrict__ proper_const, const float* __restrict__ proper_mul, int n_proper,
    int gb, int ga, int gi,
    float* __restrict__ out)
{
    int lane = threadIdx.x & 31;
    int warp = threadIdx.x >> 5;

    int cat, bstart, bcount;
    int bx = blockIdx.x;
    if (bx < gb)      { cat = 0; bstart = 0;  bcount = gb; }
    else if (bx < ga) { cat = 1; bstart = gb; bcount = ga - gb; }
    else if (bx < gi) { cat = 2; bstart = ga; bcount = gi - ga; }
    else              { cat = 3; bstart = gi; bcount = gridDim.x - gi; }

    int warp_g = (bx - bstart) * NWARP + warp;
    int nwarps = bcount * NWARP;
    float ex = 0.0f, ey = 0.0f;

    if (cat == 0) {                 // bonds (cheap; single)
        for (int t = warp_g; t < n_bond; t += nwarps) {
            int a0 = __ldg(&bond_idcs[2 * t]);
            int a1 = __ldg(&bond_idcs[2 * t + 1]);
            int ty = __ldg(&bond_type[t]);
            float eq = __ldg(&equ_bond[ty]);
            float kb = __ldg(&k_bond[ty]);
            float2 x0, y0, z0, x1, y1, z1;
            load_atom(a0, lane, x0, y0, z0);
            load_atom(a1, lane, x1, y1, z1);
            float2 dx = f2sub(x0, x1), dy = f2sub(y0, y1), dz = f2sub(z0, z1);
            float2 r2 = f2dot3(dx, dy, dz, dx, dy, dz);
            float ddx = sqrtf(r2.x) - eq;
            float ddy = sqrtf(r2.y) - eq;
            ex = fmaf(kb * ddx, ddx, ex);
            ey = fmaf(kb * ddy, ddy, ey);
        }
    } else if (cat == 1) {          // angles, unroll 2
        int t = warp_g;
        for (; t + nwarps < n_angle; t += 2 * nwarps) {
            angle_term(t,          lane, angle_idcs, angle_type, equ_angle, k_angle, ex, ey);
            angle_term(t + nwarps, lane, angle_idcs, angle_type, equ_angle, k_angle, ex, ey);
        }
        if (t < n_angle)
            angle_term(t, lane, angle_idcs, angle_type, equ_angle, k_angle, ex, ey);
    } else if (cat == 2) {          // impropers, unroll 2
        int t = warp_g;
        for (; t + nwarps < n_improper; t += 2 * nwarps) {
            improper_term(t,          lane, improper_idcs, improper_type, equ_improper, k_improper, ex, ey);
            improper_term(t + nwarps, lane, improper_idcs, improper_type, equ_improper, k_improper, ex, ey);
        }
        if (t < n_improper)
            improper_term(t, lane, improper_idcs, improper_type, equ_improper, k_improper, ex, ey);
    } else {                        // propers, unroll 2
        int t = warp_g;
        for (; t + nwarps < n_proper; t += 2 * nwarps) {
            proper_term(t,          lane, proper_idcs, proper_phase, proper_const, proper_mul, ex, ey);
            proper_term(t + nwarps, lane, proper_idcs, proper_phase, proper_const, proper_mul, ex, ey);
        }
        if (t < n_proper)
            proper_term(t, lane, proper_idcs, proper_phase, proper_const, proper_mul, ex, ey);
    }

    // Per-warp private slots, then fold.
    __shared__ float sh[NWARP][NB];
    sh[warp][2 * lane]     = ex;
    sh[warp][2 * lane + 1] = ey;
    __syncthreads();
    if (threadIdx.x < NB) {
        float s = 0.0f;
        #pragma unroll
        for (int w = 0; w < NWARP; w++) s += sh[w][threadIdx.x];
        atomicAdd(&out[threadIdx.x], s);
    }
}

extern "C" void kernel_launch(void* const* d_in, const int* in_sizes, int n_in,
                              void* d_out, int out_size) {
    const float* pos            = (const float*)d_in[0];
    const int*   bond_idcs      = (const int*)d_in[1];
    const int*   bond_type      = (const int*)d_in[2];
    const float* equ_bond       = (const float*)d_in[3];
    const float* k_bond         = (const float*)d_in[4];
    const int*   angle_idcs     = (const int*)d_in[5];
    const int*   angle_type     = (const int*)d_in[6];
    const float* equ_angle      = (const float*)d_in[7];
    const float* k_angle        = (const float*)d_in[8];
    const int*   improper_idcs  = (const int*)d_in[9];
    const int*   improper_type  = (const int*)d_in[10];
    const float* equ_improper   = (const float*)d_in[11];
    const float* k_improper     = (const float*)d_in[12];
    const int*   proper_idcs    = (const int*)d_in[13];
    const float* proper_phase   = (const float*)d_in[14];
    const float* proper_const   = (const float*)d_in[15];
    const float* proper_mul     = (const float*)d_in[16];
    float* out = (float*)d_out;

    int B          = out_size;              // 64
    int n_bond     = in_sizes[2];
    int n_angle    = in_sizes[6];
    int n_improper = in_sizes[10];
    int n_proper   = in_sizes[14];
    int n_atoms    = in_sizes[0] / (3 * B);

    int tr_blocks = (n_atoms + TR_ATOMS - 1) / TR_ATOMS;
    transpose_kernel<<<tr_blocks, TPB>>>(pos, n_atoms, out);

    // 888 blocks; with ~5 blocks/SM resident this still fills in ~1-2 short waves.
    // Cost weights per term: bond 6, angle 10, improper 15, proper 12.
    long long wb = 6LL * n_bond, wa = 10LL * n_angle, wi = 15LL * n_improper, wp = 12LL * n_proper;
    long long wt = wb + wa + wi + wp;
    int total_blocks = 888;
    int gb  = (int)(total_blocks * wb / wt); if (gb < 1) gb = 1;
    int ga_ = (int)(total_blocks * wa / wt); if (ga_ < 1) ga_ = 1;
    int gi_ = (int)(total_blocks * wi / wt); if (gi_ < 1) gi_ = 1;
    int ga = gb + ga_;
    int gi = ga + gi_;
    if (gi >= total_blocks) gi = total_blocks - 1;

    energy_kernel<<<total_blocks, TPB>>>(
        bond_idcs, bond_type, equ_bond, k_bond, n_bond,
        angle_idcs, angle_type, equ_angle, k_angle, n_angle,
        improper_idcs, improper_type, equ_improper, k_improper, n_improper,
        proper_idcs, proper_phase, proper_const, proper_mul, n_proper,
        gb, ga, gi, out);
}

// round 12
// speedup vs baseline: 1.3012x; 1.1965x over previous
#include <cuda_runtime.h>
#include <cuda_bf16.h>

#define TPB 256
#define MAX_ATOMS 100000
#define NB 64
#define NB2 32   // float2 pairs per atom
#define NWARP (TPB / 32)
#define TR_ATOMS 32

// Interleaved batch-fastest positions: g_pos[atom][comp][pair] as float2.
// One address per atom; x/y/z at +0/+256/+512 bytes. Lane l covers batches
// 2l, 2l+1 -> every load is a coalesced 256B run.
__device__ float2 g_pos[(size_t)MAX_ATOMS * 3 * NB2];

// Tiled transpose: pos[b][atom][3] -> g_pos[atom][comp][pair]. Zeroes out[].
__global__ void transpose_kernel(const float* __restrict__ pos, int n_atoms,
                                 float* __restrict__ out) {
    __shared__ float tile[NB][TR_ATOMS * 3 + 1];   // [64][97]
    int tid = threadIdx.x;
    int atom_base = blockIdx.x * TR_ATOMS;

    if (blockIdx.x == 0 && tid < NB) out[tid] = 0.0f;

    int lim3 = n_atoms * 3;
    int base3 = atom_base * 3;
    #pragma unroll
    for (int idx = tid; idx < NB * (TR_ATOMS * 3 / 4); idx += TPB) {
        int b = idx / (TR_ATOMS * 3 / 4);
        int q = idx - b * (TR_ATOMS * 3 / 4);
        int g = base3 + q * 4;
        if (g + 3 < lim3) {
            float4 v = __ldg((const float4*)(pos + (size_t)b * lim3 + g));
            tile[b][q * 4]     = v.x;
            tile[b][q * 4 + 1] = v.y;
            tile[b][q * 4 + 2] = v.z;
            tile[b][q * 4 + 3] = v.w;
        } else {
            for (int k = 0; k < 4 && g + k < lim3; k++)
                tile[b][q * 4 + k] = __ldg(&pos[(size_t)b * lim3 + g + k]);
        }
    }
    __syncthreads();
    #pragma unroll
    for (int idx = tid; idx < 3 * TR_ATOMS * NB2; idx += TPB) {
        int comp = idx >> 10;
        int rem  = idx & 1023;
        int atom = rem >> 5;
        int l    = rem & 31;
        int ga = atom_base + atom;
        if (ga < n_atoms) {
            float2 v = make_float2(tile[2 * l][atom * 3 + comp],
                                   tile[2 * l + 1][atom * 3 + comp]);
            g_pos[(size_t)ga * (3 * NB2) + comp * NB2 + l] = v;
        }
    }
}

// ---- float2 elementwise helpers ----
__device__ __forceinline__ float2 f2sub(float2 a, float2 b) { return make_float2(a.x - b.x, a.y - b.y); }
__device__ __forceinline__ float2 f2mul(float2 a, float2 b) { return make_float2(a.x * b.x, a.y * b.y); }
__device__ __forceinline__ float2 f2fma(float2 a, float2 b, float2 c) {
    return make_float2(fmaf(a.x, b.x, c.x), fmaf(a.y, b.y, c.y));
}
__device__ __forceinline__ float2 f2nfma(float2 a, float2 b, float2 c) { // c - a*b
    return make_float2(fmaf(-a.x, b.x, c.x), fmaf(-a.y, b.y, c.y));
}
__device__ __forceinline__ float2 f2rsqrt(float2 a) { return make_float2(rsqrtf(a.x), rsqrtf(a.y)); }

__device__ __forceinline__ void load_atom(int a, int lane, float2& x, float2& y, float2& z) {
    const float2* p = g_pos + (size_t)a * (3 * NB2) + lane;
    x = __ldg(p);
    y = __ldg(p + NB2);
    z = __ldg(p + 2 * NB2);
}

__device__ __forceinline__ float2 f2dot3(float2 ax, float2 ay, float2 az,
                                         float2 bx, float2 by, float2 bz) {
    return f2fma(ax, bx, f2fma(ay, by, f2mul(az, bz)));
}

// Abramowitz-Stegun 4.4.46 degree-7: |err| ~ 1e-7 over [-1, 1].
__device__ __forceinline__ float fast_acos(float x) {
    float a = fabsf(x);
    float p = fmaf(a, -0.0012624911f, 0.0066700901f);
    p = fmaf(a, p, -0.0170881256f);
    p = fmaf(a, p, 0.0308918810f);
    p = fmaf(a, p, -0.0501743046f);
    p = fmaf(a, p, 0.0889789874f);
    p = fmaf(a, p, -0.2145988016f);
    p = fmaf(a, p, 1.5707963050f);
    float r = p * sqrtf(1.0f - a);
    return (x < 0.0f) ? (3.14159265358979f - r) : r;
}

// Minimax odd atan on [0,1] + quadrant reduction; |err| ~ 1e-6.
__device__ __forceinline__ float fast_atan2(float y, float x) {
    float ax = fabsf(x), ay = fabsf(y);
    float mx = fmaxf(ax, ay), mn = fminf(ax, ay);
    float z = __fdividef(mn, mx);
    float z2 = z * z;
    float p = fmaf(z2, -0.0117212f, 0.0526533f);
    p = fmaf(z2, p, -0.1164329f);
    p = fmaf(z2, p, 0.1935435f);
    p = fmaf(z2, p, -0.3326235f);
    p = fmaf(z2, p, 0.9999773f);
    float r = p * z;
    if (ay > ax) r = 1.57079632679f - r;
    if (x < 0.0f) r = 3.14159265359f - r;
    return copysignf(r, y);
}

// Raw dihedral numerator/denominator (x, y) for a batch-pair; phi = atan2(y, x).
__device__ __forceinline__ void dihedral_xy(int a0, int a1, int a2, int a3, int lane,
                                            float2& X, float2& Y) {
    float2 x0, y0, z0, x1, y1, z1, x2, y2, z2, x3, y3, z3;
    load_atom(a0, lane, x0, y0, z0);
    load_atom(a1, lane, x1, y1, z1);
    load_atom(a2, lane, x2, y2, z2);
    load_atom(a3, lane, x3, y3, z3);
    float2 b0x = f2sub(x0, x1), b0y = f2sub(y0, y1), b0z = f2sub(z0, z1);
    float2 b1x = f2sub(x2, x1), b1y = f2sub(y2, y1), b1z = f2sub(z2, z1);
    float2 b2x = f2sub(x3, x2), b2y = f2sub(y3, y2), b2z = f2sub(z3, z2);
    float2 inv = f2rsqrt(f2dot3(b1x, b1y, b1z, b1x, b1y, b1z));
    b1x = f2mul(b1x, inv); b1y = f2mul(b1y, inv); b1z = f2mul(b1z, inv);
    float2 d0 = f2dot3(b0x, b0y, b0z, b1x, b1y, b1z);
    float2 d2 = f2dot3(b2x, b2y, b2z, b1x, b1y, b1z);
    float2 vx = f2nfma(d0, b1x, b0x), vy = f2nfma(d0, b1y, b0y), vz = f2nfma(d0, b1z, b0z);
    float2 wx = f2nfma(d2, b1x, b2x), wy = f2nfma(d2, b1y, b2y), wz = f2nfma(d2, b1z, b2z);
    X = f2dot3(vx, vy, vz, wx, wy, wz);
    float2 cx = f2sub(f2mul(b1y, vz), f2mul(b1z, vy));
    float2 cy = f2sub(f2mul(b1z, vx), f2mul(b1x, vz));
    float2 cz = f2sub(f2mul(b1x, vy), f2mul(b1y, vx));
    Y = f2dot3(cx, cy, cz, wx, wy, wz);
}

// Partitioned kernel with index-only software pipelining: next iteration's
// term indices are loaded before the current term's math, hiding one L2
// round-trip per iteration. launch_bounds pins 6 blocks/SM.
__global__ void __launch_bounds__(TPB, 6) energy_kernel(
    const int* __restrict__ bond_idcs, const int* __restrict__ bond_type,
    const float* __restrict__ equ_bond, const float* __restrict__ k_bond, int n_bond,
    const int* __restrict__ angle_idcs, const int* __restrict__ angle_type,
    const float* __restrict__ equ_angle, const float* __restrict__ k_angle, int n_angle,
    const int* __restrict__ improper_idcs, const int* __restrict__ improper_type,
    const float* __restrict__ equ_improper, const float* __restrict__ k_improper, int n_improper,
    const int* __restrict__ proper_idcs, const float* __restrict__ proper_phase,
    const float* __restrict__ proper_const, const float* __restrict__ proper_mul, int n_proper,
    int gb, int ga, int gi,
    float* __restrict__ out)
{
    int lane = threadIdx.x & 31;
    int warp = threadIdx.x >> 5;

    int cat, bstart, bcount;
    int bx = blockIdx.x;
    if (bx < gb)      { cat = 0; bstart = 0;  bcount = gb; }
    else if (bx < ga) { cat = 1; bstart = gb; bcount = ga - gb; }
    else if (bx < gi) { cat = 2; bstart = ga; bcount = gi - ga; }
    else              { cat = 3; bstart = gi; bcount = gridDim.x - gi; }

    int warp_g = (bx - bstart) * NWARP + warp;
    int nwarps = bcount * NWARP;
    float ex = 0.0f, ey = 0.0f;

    if (cat == 0) {                 // bonds
        int t = warp_g;
        if (t < n_bond) {
            int a0 = __ldg(&bond_idcs[2 * t]);
            int a1 = __ldg(&bond_idcs[2 * t + 1]);
            int ty = __ldg(&bond_type[t]);
            for (;;) {
                int tn = t + nwarps;
                int b0, b1, tyn;
                bool more = tn < n_bond;
                if (more) {
                    b0  = __ldg(&bond_idcs[2 * tn]);
                    b1  = __ldg(&bond_idcs[2 * tn + 1]);
                    tyn = __ldg(&bond_type[tn]);
                }
                float eq = __ldg(&equ_bond[ty]);
                float kb = __ldg(&k_bond[ty]);
                float2 x0, y0, z0, x1, y1, z1;
                load_atom(a0, lane, x0, y0, z0);
                load_atom(a1, lane, x1, y1, z1);
                float2 dx = f2sub(x0, x1), dy = f2sub(y0, y1), dz = f2sub(z0, z1);
                float2 r2 = f2dot3(dx, dy, dz, dx, dy, dz);
                float ddx = sqrtf(r2.x) - eq;
                float ddy = sqrtf(r2.y) - eq;
                ex = fmaf(kb * ddx, ddx, ex);
                ey = fmaf(kb * ddy, ddy, ey);
                if (!more) break;
                t = tn; a0 = b0; a1 = b1; ty = tyn;
            }
        }
    } else if (cat == 1) {          // angles
        int t = warp_g;
        if (t < n_angle) {
            int a0 = __ldg(&angle_idcs[3 * t]);
            int a1 = __ldg(&angle_idcs[3 * t + 1]);
            int a2 = __ldg(&angle_idcs[3 * t + 2]);
            int ty = __ldg(&angle_type[t]);
            for (;;) {
                int tn = t + nwarps;
                int b0, b1, b2, tyn;
                bool more = tn < n_angle;
                if (more) {
                    b0  = __ldg(&angle_idcs[3 * tn]);
                    b1  = __ldg(&angle_idcs[3 * tn + 1]);
                    b2  = __ldg(&angle_idcs[3 * tn + 2]);
                    tyn = __ldg(&angle_type[tn]);
                }
                float eq = __ldg(&equ_angle[ty]);
                float ka = __ldg(&k_angle[ty]);
                float2 x0, y0, z0, x1, y1, z1, x2, y2, z2;
                load_atom(a0, lane, x0, y0, z0);
                load_atom(a1, lane, x1, y1, z1);
                load_atom(a2, lane, x2, y2, z2);
                float2 v1x = f2sub(x0, x1), v1y = f2sub(y0, y1), v1z = f2sub(z0, z1);
                float2 v2x = f2sub(x2, x1), v2y = f2sub(y2, y1), v2z = f2sub(z2, z1);
                float2 n1 = f2dot3(v1x, v1y, v1z, v1x, v1y, v1z);
                float2 n2 = f2dot3(v2x, v2y, v2z, v2x, v2y, v2z);
                float2 dt = f2dot3(v1x, v1y, v1z, v2x, v2y, v2z);
                float2 c = f2mul(f2mul(dt, f2rsqrt(n1)), f2rsqrt(n2));
                float cx = fminf(1.0f, fmaxf(-1.0f, c.x));
                float cy = fminf(1.0f, fmaxf(-1.0f, c.y));
                float ddx = fast_acos(cx) - eq;
                float ddy = fast_acos(cy) - eq;
                ex = fmaf(ka * ddx, ddx, ex);
                ey = fmaf(ka * ddy, ddy, ey);
                if (!more) break;
                t = tn; a0 = b0; a1 = b1; a2 = b2; ty = tyn;
            }
        }
    } else if (cat == 2) {          // impropers
        int t = warp_g;
        if (t < n_improper) {
            int4 a = __ldg((const int4*)improper_idcs + t);
            int ty = __ldg(&improper_type[t]);
            for (;;) {
                int tn = t + nwarps;
                int4 an;
                int tyn;
                bool more = tn < n_improper;
                if (more) {
                    an  = __ldg((const int4*)improper_idcs + tn);
                    tyn = __ldg(&improper_type[tn]);
                }
                float eq = __ldg(&equ_improper[ty]);
                float ki = __ldg(&k_improper[ty]);
                float2 X, Y;
                dihedral_xy(a.x, a.y, a.z, a.w, lane, X, Y);
                float ddx = fast_atan2(Y.x, X.x) - eq;
                float ddy = fast_atan2(Y.y, X.y) - eq;
                ex = fmaf(ki * ddx, ddx, ex);
                ey = fmaf(ki * ddy, ddy, ey);
                if (!more) break;
                t = tn; a = an; ty = tyn;
            }
        }
    } else {                        // propers
        int t = warp_g;
        if (t < n_proper) {
            int4 a = __ldg((const int4*)proper_idcs + t);
            for (;;) {
                int tn = t + nwarps;
                int4 an;
                bool more = tn < n_proper;
                if (more) an = __ldg((const int4*)proper_idcs + tn);
                float ph  = __ldg(&proper_phase[t]);
                float cst = __ldg(&proper_const[t]);
                float ml  = __ldg(&proper_mul[t]);
                float2 X, Y;
                dihedral_xy(a.x, a.y, a.z, a.w, lane, X, Y);
                if (ml == 2.0f && ph == 0.0f) {
                    // cst*(1+cos(2*atan2(y,x))) = 2*cst*x^2/(x^2+y^2)
                    float c2x = 2.0f * cst;
                    ex = fmaf(c2x * X.x, X.x / fmaf(X.x, X.x, Y.x * Y.x), ex);
                    ey = fmaf(c2x * X.y, X.y / fmaf(X.y, X.y, Y.y * Y.y), ey);
                } else {
                    float phix = fast_atan2(Y.x, X.x);
                    float phiy = fast_atan2(Y.y, X.y);
                    ex += cst * (1.0f + cosf(fmaf(ml, phix, -ph)));
                    ey += cst * (1.0f + cosf(fmaf(ml, phiy, -ph)));
                }
                if (!more) break;
                t = tn; a = an;
            }
        }
    }

    // Per-warp private slots, then fold.
    __shared__ float sh[NWARP][NB];
    sh[warp][2 * lane]     = ex;
    sh[warp][2 * lane + 1] = ey;
    __syncthreads();
    if (threadIdx.x < NB) {
        float s = 0.0f;
        #pragma unroll
        for (int w = 0; w < NWARP; w++) s += sh[w][threadIdx.x];
        atomicAdd(&out[threadIdx.x], s);
    }
}

extern "C" void kernel_launch(void* const* d_in, const int* in_sizes, int n_in,
                              void* d_out, int out_size) {
    const float* pos            = (const float*)d_in[0];
    const int*   bond_idcs      = (const int*)d_in[1];
    const int*   bond_type      = (const int*)d_in[2];
    const float* equ_bond       = (const float*)d_in[3];
    const float* k_bond         = (const float*)d_in[4];
    const int*   angle_idcs     = (const int*)d_in[5];
    const int*   angle_type     = (const int*)d_in[6];
    const float* equ_angle      = (const float*)d_in[7];
    const float* k_angle        = (const float*)d_in[8];
    const int*   improper_idcs  = (const int*)d_in[9];
    const int*   improper_type  = (const int*)d_in[10];
    const float* equ_improper   = (const float*)d_in[11];
    const float* k_improper     = (const float*)d_in[12];
    const int*   proper_idcs    = (const int*)d_in[13];
    const float* proper_phase   = (const float*)d_in[14];
    const float* proper_const   = (const float*)d_in[15];
    const float* proper_mul     = (const float*)d_in[16];
    float* out = (float*)d_out;

    int B          = out_size;              // 64
    int n_bond     = in_sizes[2];
    int n_angle    = in_sizes[6];
    int n_improper = in_sizes[10];
    int n_proper   = in_sizes[14];
    int n_atoms    = in_sizes[0] / (3 * B);

    int tr_blocks = (n_atoms + TR_ATOMS - 1) / TR_ATOMS;
    transpose_kernel<<<tr_blocks, TPB>>>(pos, n_atoms, out);

    // Single wave: 888 blocks = 6 blocks/SM x 148 SMs.
    // Cost weights per term: bond 6, angle 10, improper 15, proper 12.
    long long wb = 6LL * n_bond, wa = 10LL * n_angle, wi = 15LL * n_improper, wp = 12LL * n_proper;
    long long wt = wb + wa + wi + wp;
    int total_blocks = 888;
    int gb  = (int)(total_blocks * wb / wt); if (gb < 1) gb = 1;
    int ga_ = (int)(total_blocks * wa / wt); if (ga_ < 1) ga_ = 1;
    int gi_ = (int)(total_blocks * wi / wt); if (gi_ < 1) gi_ = 1;
    int ga = gb + ga_;
    int gi = ga + gi_;
    if (gi >= total_blocks) gi = total_blocks - 1;

    energy_kernel<<<total_blocks, TPB>>>(
        bond_idcs, bond_type, equ_bond, k_bond, n_bond,
        angle_idcs, angle_type, equ_angle, k_angle, n_angle,
        improper_idcs, improper_type, equ_improper, k_improper, n_improper,
        proper_idcs, proper_phase, proper_const, proper_mul, n_proper,
        gb, ga, gi, out);
}

// round 13
// speedup vs baseline: 1.4839x; 1.1404x over previous
#include <cuda_runtime.h>
#include <cuda_bf16.h>

#define TPB 256
#define MAX_ATOMS 100000
#define NB 64
#define NB2 32   // float2 pairs per atom
#define NWARP (TPB / 32)
#define TR_ATOMS 32

// Interleaved batch-fastest positions: g_pos[atom][comp][pair] as float2.
// One address per atom; x/y/z at +0/+256/+512 bytes. Lane l covers batches
// 2l, 2l+1 -> every load is a coalesced 256B run.
__device__ float2 g_pos[(size_t)MAX_ATOMS * 3 * NB2];

// Tiled transpose: pos[b][atom][3] -> g_pos[atom][comp][pair]. Zeroes out[].
__global__ void transpose_kernel(const float* __restrict__ pos, int n_atoms,
                                 float* __restrict__ out) {
    __shared__ float tile[NB][TR_ATOMS * 3 + 1];   // [64][97]
    int tid = threadIdx.x;
    int atom_base = blockIdx.x * TR_ATOMS;

    if (blockIdx.x == 0 && tid < NB) out[tid] = 0.0f;

    int lim3 = n_atoms * 3;
    int base3 = atom_base * 3;
    #pragma unroll
    for (int idx = tid; idx < NB * (TR_ATOMS * 3 / 4); idx += TPB) {
        int b = idx / (TR_ATOMS * 3 / 4);
        int q = idx - b * (TR_ATOMS * 3 / 4);
        int g = base3 + q * 4;
        if (g + 3 < lim3) {
            float4 v = __ldg((const float4*)(pos + (size_t)b * lim3 + g));
            tile[b][q * 4]     = v.x;
            tile[b][q * 4 + 1] = v.y;
            tile[b][q * 4 + 2] = v.z;
            tile[b][q * 4 + 3] = v.w;
        } else {
            for (int k = 0; k < 4 && g + k < lim3; k++)
                tile[b][q * 4 + k] = __ldg(&pos[(size_t)b * lim3 + g + k]);
        }
    }
    __syncthreads();
    #pragma unroll
    for (int idx = tid; idx < 3 * TR_ATOMS * NB2; idx += TPB) {
        int comp = idx >> 10;
        int rem  = idx & 1023;
        int atom = rem >> 5;
        int l    = rem & 31;
        int ga = atom_base + atom;
        if (ga < n_atoms) {
            float2 v = make_float2(tile[2 * l][atom * 3 + comp],
                                   tile[2 * l + 1][atom * 3 + comp]);
            g_pos[(size_t)ga * (3 * NB2) + comp * NB2 + l] = v;
        }
    }
}

// ---- float2 elementwise helpers ----
__device__ __forceinline__ float2 f2sub(float2 a, float2 b) { return make_float2(a.x - b.x, a.y - b.y); }
__device__ __forceinline__ float2 f2mul(float2 a, float2 b) { return make_float2(a.x * b.x, a.y * b.y); }
__device__ __forceinline__ float2 f2fma(float2 a, float2 b, float2 c) {
    return make_float2(fmaf(a.x, b.x, c.x), fmaf(a.y, b.y, c.y));
}
__device__ __forceinline__ float2 f2nfma(float2 a, float2 b, float2 c) { // c - a*b
    return make_float2(fmaf(-a.x, b.x, c.x), fmaf(-a.y, b.y, c.y));
}
__device__ __forceinline__ float2 f2rsqrt(float2 a) { return make_float2(rsqrtf(a.x), rsqrtf(a.y)); }

__device__ __forceinline__ void load_atom(int a, int lane, float2& x, float2& y, float2& z) {
    const float2* p = g_pos + (size_t)a * (3 * NB2) + lane;
    x = __ldg(p);
    y = __ldg(p + NB2);
    z = __ldg(p + 2 * NB2);
}

__device__ __forceinline__ float2 f2dot3(float2 ax, float2 ay, float2 az,
                                         float2 bx, float2 by, float2 bz) {
    return f2fma(ax, bx, f2fma(ay, by, f2mul(az, bz)));
}

// Abramowitz-Stegun 4.4.46 degree-7: |err| ~ 1e-7 over [-1, 1].
__device__ __forceinline__ float fast_acos(float x) {
    float a = fabsf(x);
    float p = fmaf(a, -0.0012624911f, 0.0066700901f);
    p = fmaf(a, p, -0.0170881256f);
    p = fmaf(a, p, 0.0308918810f);
    p = fmaf(a, p, -0.0501743046f);
    p = fmaf(a, p, 0.0889789874f);
    p = fmaf(a, p, -0.2145988016f);
    p = fmaf(a, p, 1.5707963050f);
    float r = p * sqrtf(1.0f - a);
    return (x < 0.0f) ? (3.14159265358979f - r) : r;
}

// Minimax odd atan on [0,1] + quadrant reduction; |err| ~ 1e-6.
__device__ __forceinline__ float fast_atan2(float y, float x) {
    float ax = fabsf(x), ay = fabsf(y);
    float mx = fmaxf(ax, ay), mn = fminf(ax, ay);
    float z = __fdividef(mn, mx);
    float z2 = z * z;
    float p = fmaf(z2, -0.0117212f, 0.0526533f);
    p = fmaf(z2, p, -0.1164329f);
    p = fmaf(z2, p, 0.1935435f);
    p = fmaf(z2, p, -0.3326235f);
    p = fmaf(z2, p, 0.9999773f);
    float r = p * z;
    if (ay > ax) r = 1.57079632679f - r;
    if (x < 0.0f) r = 3.14159265359f - r;
    return copysignf(r, y);
}

// Raw dihedral numerator/denominator (x, y) for a batch-pair; phi = atan2(y, x).
__device__ __forceinline__ void dihedral_xy(int a0, int a1, int a2, int a3, int lane,
                                            float2& X, float2& Y) {
    float2 x0, y0, z0, x1, y1, z1, x2, y2, z2, x3, y3, z3;
    load_atom(a0, lane, x0, y0, z0);
    load_atom(a1, lane, x1, y1, z1);
    load_atom(a2, lane, x2, y2, z2);
    load_atom(a3, lane, x3, y3, z3);
    float2 b0x = f2sub(x0, x1), b0y = f2sub(y0, y1), b0z = f2sub(z0, z1);
    float2 b1x = f2sub(x2, x1), b1y = f2sub(y2, y1), b1z = f2sub(z2, z1);
    float2 b2x = f2sub(x3, x2), b2y = f2sub(y3, y2), b2z = f2sub(z3, z2);
    float2 inv = f2rsqrt(f2dot3(b1x, b1y, b1z, b1x, b1y, b1z));
    b1x = f2mul(b1x, inv); b1y = f2mul(b1y, inv); b1z = f2mul(b1z, inv);
    float2 d0 = f2dot3(b0x, b0y, b0z, b1x, b1y, b1z);
    float2 d2 = f2dot3(b2x, b2y, b2z, b1x, b1y, b1z);
    float2 vx = f2nfma(d0, b1x, b0x), vy = f2nfma(d0, b1y, b0y), vz = f2nfma(d0, b1z, b0z);
    float2 wx = f2nfma(d2, b1x, b2x), wy = f2nfma(d2, b1y, b2y), wz = f2nfma(d2, b1z, b2z);
    X = f2dot3(vx, vy, vz, wx, wy, wz);
    float2 cx = f2sub(f2mul(b1y, vz), f2mul(b1z, vy));
    float2 cy = f2sub(f2mul(b1z, vx), f2mul(b1x, vz));
    float2 cz = f2sub(f2mul(b1x, vy), f2mul(b1y, vx));
    Y = f2dot3(cx, cy, cz, wx, wy, wz);
}

// All blocks walk ALL four categories as sequential tight loops with
// grid-wide warp stride: perfect load balance, no partition weights, no
// per-iteration category branch. Lane l covers batches 2l, 2l+1.
__global__ void energy_kernel(
    const int* __restrict__ bond_idcs, const int* __restrict__ bond_type,
    const float* __restrict__ equ_bond, const float* __restrict__ k_bond, int n_bond,
    const int* __restrict__ angle_idcs, const int* __restrict__ angle_type,
    const float* __restrict__ equ_angle, const float* __restrict__ k_angle, int n_angle,
    const int* __restrict__ improper_idcs, const int* __restrict__ improper_type,
    const float* __restrict__ equ_improper, const float* __restrict__ k_improper, int n_improper,
    const int* __restrict__ proper_idcs, const float* __restrict__ proper_phase,
    const float* __restrict__ proper_const, const float* __restrict__ proper_mul, int n_proper,
    float* __restrict__ out)
{
    int lane = threadIdx.x & 31;
    int warp = threadIdx.x >> 5;
    int warp_g = blockIdx.x * NWARP + warp;
    int nwarps = gridDim.x * NWARP;
    float ex = 0.0f, ey = 0.0f;

    // bonds
    for (int t = warp_g; t < n_bond; t += nwarps) {
        int a0 = __ldg(&bond_idcs[2 * t]);
        int a1 = __ldg(&bond_idcs[2 * t + 1]);
        int ty = __ldg(&bond_type[t]);
        float eq = __ldg(&equ_bond[ty]);
        float kb = __ldg(&k_bond[ty]);
        float2 x0, y0, z0, x1, y1, z1;
        load_atom(a0, lane, x0, y0, z0);
        load_atom(a1, lane, x1, y1, z1);
        float2 dx = f2sub(x0, x1), dy = f2sub(y0, y1), dz = f2sub(z0, z1);
        float2 r2 = f2dot3(dx, dy, dz, dx, dy, dz);
        float ddx = sqrtf(r2.x) - eq;
        float ddy = sqrtf(r2.y) - eq;
        ex = fmaf(kb * ddx, ddx, ex);
        ey = fmaf(kb * ddy, ddy, ey);
    }

    // angles
    for (int t = warp_g; t < n_angle; t += nwarps) {
        int a0 = __ldg(&angle_idcs[3 * t]);
        int a1 = __ldg(&angle_idcs[3 * t + 1]);
        int a2 = __ldg(&angle_idcs[3 * t + 2]);
        int ty = __ldg(&angle_type[t]);
        float eq = __ldg(&equ_angle[ty]);
        float ka = __ldg(&k_angle[ty]);
        float2 x0, y0, z0, x1, y1, z1, x2, y2, z2;
        load_atom(a0, lane, x0, y0, z0);
        load_atom(a1, lane, x1, y1, z1);
        load_atom(a2, lane, x2, y2, z2);
        float2 v1x = f2sub(x0, x1), v1y = f2sub(y0, y1), v1z = f2sub(z0, z1);
        float2 v2x = f2sub(x2, x1), v2y = f2sub(y2, y1), v2z = f2sub(z2, z1);
        float2 n1 = f2dot3(v1x, v1y, v1z, v1x, v1y, v1z);
        float2 n2 = f2dot3(v2x, v2y, v2z, v2x, v2y, v2z);
        float2 dt = f2dot3(v1x, v1y, v1z, v2x, v2y, v2z);
        float2 c = f2mul(f2mul(dt, f2rsqrt(n1)), f2rsqrt(n2));
        float cx = fminf(1.0f, fmaxf(-1.0f, c.x));
        float cy = fminf(1.0f, fmaxf(-1.0f, c.y));
        float ddx = fast_acos(cx) - eq;
        float ddy = fast_acos(cy) - eq;
        ex = fmaf(ka * ddx, ddx, ex);
        ey = fmaf(ka * ddy, ddy, ey);
    }

    // impropers
    for (int t = warp_g; t < n_improper; t += nwarps) {
        int4 a = __ldg((const int4*)improper_idcs + t);
        int ty = __ldg(&improper_type[t]);
        float eq = __ldg(&equ_improper[ty]);
        float ki = __ldg(&k_improper[ty]);
        float2 X, Y;
        dihedral_xy(a.x, a.y, a.z, a.w, lane, X, Y);
        float ddx = fast_atan2(Y.x, X.x) - eq;
        float ddy = fast_atan2(Y.y, X.y) - eq;
        ex = fmaf(ki * ddx, ddx, ex);
        ey = fmaf(ki * ddy, ddy, ey);
    }

    // propers
    for (int t = warp_g; t < n_proper; t += nwarps) {
        int4 a = __ldg((const int4*)proper_idcs + t);
        float ph  = __ldg(&proper_phase[t]);
        float cst = __ldg(&proper_const[t]);
        float ml  = __ldg(&proper_mul[t]);
        float2 X, Y;
        dihedral_xy(a.x, a.y, a.z, a.w, lane, X, Y);
        if (ml == 2.0f && ph == 0.0f) {
            // cst*(1+cos(2*atan2(y,x))) = 2*cst*x^2/(x^2+y^2)
            float c2x = 2.0f * cst;
            ex = fmaf(c2x * X.x, X.x / fmaf(X.x, X.x, Y.x * Y.x), ex);
            ey = fmaf(c2x * X.y, X.y / fmaf(X.y, X.y, Y.y * Y.y), ey);
        } else {
            float phix = fast_atan2(Y.x, X.x);
            float phiy = fast_atan2(Y.y, X.y);
            ex += cst * (1.0f + cosf(fmaf(ml, phix, -ph)));
            ey += cst * (1.0f + cosf(fmaf(ml, phiy, -ph)));
        }
    }

    // Per-warp private slots, then fold.
    __shared__ float sh[NWARP][NB];
    sh[warp][2 * lane]     = ex;
    sh[warp][2 * lane + 1] = ey;
    __syncthreads();
    if (threadIdx.x < NB) {
        float s = 0.0f;
        #pragma unroll
        for (int w = 0; w < NWARP; w++) s += sh[w][threadIdx.x];
        atomicAdd(&out[threadIdx.x], s);
    }
}

extern "C" void kernel_launch(void* const* d_in, const int* in_sizes, int n_in,
                              void* d_out, int out_size) {
    const float* pos            = (const float*)d_in[0];
    const int*   bond_idcs      = (const int*)d_in[1];
    const int*   bond_type      = (const int*)d_in[2];
    const float* equ_bond       = (const float*)d_in[3];
    const float* k_bond         = (const float*)d_in[4];
    const int*   angle_idcs     = (const int*)d_in[5];
    const int*   angle_type     = (const int*)d_in[6];
    const float* equ_angle      = (const float*)d_in[7];
    const float* k_angle        = (const float*)d_in[8];
    const int*   improper_idcs  = (const int*)d_in[9];
    const int*   improper_type  = (const int*)d_in[10];
    const float* equ_improper   = (const float*)d_in[11];
    const float* k_improper     = (const float*)d_in[12];
    const int*   proper_idcs    = (const int*)d_in[13];
    const float* proper_phase   = (const float*)d_in[14];
    const float* proper_const   = (const float*)d_in[15];
    const float* proper_mul     = (const float*)d_in[16];
    float* out = (float*)d_out;

    int B          = out_size;              // 64
    int n_bond     = in_sizes[2];
    int n_angle    = in_sizes[6];
    int n_improper = in_sizes[10];
    int n_proper   = in_sizes[14];
    int n_atoms    = in_sizes[0] / (3 * B);

    int tr_blocks = (n_atoms + TR_ATOMS - 1) / TR_ATOMS;
    transpose_kernel<<<tr_blocks, TPB>>>(pos, n_atoms, out);

    // Single wave: 888 blocks = 6 blocks/SM x 148 SMs (regs=40 -> 6 fit).
    energy_kernel<<<888, TPB>>>(
        bond_idcs, bond_type, equ_bond, k_bond, n_bond,
        angle_idcs, angle_type, equ_angle, k_angle, n_angle,
        improper_idcs, improper_type, equ_improper, k_improper, n_improper,
        proper_idcs, proper_phase, proper_const, proper_mul, n_proper,
        out);
}